// round 6
// baseline (speedup 1.0000x reference)
#include <cuda_runtime.h>
#include <cstdint>

// ---------------- problem constants ----------------
#define Bz   8
#define Dd   4096
#define TD   512
#define WD   512
#define SLOPE 0.01f

// ---------------- scratch (static device globals) ----------------
__device__ float g_hs [Bz * 65 * Dd];
__device__ float g_q  [Bz * 65 * Dd];
__device__ float g_k  [Bz * 65 * Dd];
__device__ float g_v  [Bz * 65 * Dd];
__device__ float g_sc [Bz * 65 * 65];
__device__ float g_a  [Bz * 64 * Dd];
__device__ float g_h  [Bz * 64 * Dd];

// ================= tf32 mma.sync GEMM, fragment-layout smem =================
// C[z][M,4096] = A[M,K] @ W[z][K,4096] + bias[z] (+leaky)
// CTA tile 128m x 256n, BK=32, 512 threads, warp grid 4m x 4n, warp tile 32x64.
// Smem holds tf32 bits pre-arranged in mma fragment layout:
//   A: [ks(4)][m16tile(8)][lane(32)][reg(4)]   block=128f, padded stride 132f,
//      ks stride 8*132+4 = 1060f
//   B: [ks(4)][n16pair(16)][lane(32)][reg(4)]  ks stride 16*132+4 = 2116f
// Inner loop: 2+4 LDS.128 + 16 MMA per ks.

#define A_KS_STRIDE 1060
#define B_KS_STRIDE 2116
#define B_BASE      4240                   // 4*1060
#define STAGE_F     (B_BASE + 4 * B_KS_STRIDE)   // 12704 floats
#define GEMM_SMEM   (2 * STAGE_F * 4)            // 101632 bytes

__device__ __forceinline__ uint32_t f2tf32(float x) {
    uint32_t u;
    asm("cvt.rna.tf32.f32 %0, %1;" : "=r"(u) : "f"(x));
    return u;
}

__global__ __launch_bounds__(512, 1)
void mma_gemm(const float* __restrict__ A,
              const float* __restrict__ W0, const float* __restrict__ W1,
              const float* __restrict__ W2,
              const float* __restrict__ b0, const float* __restrict__ b1,
              const float* __restrict__ b2,
              float* __restrict__ C0, float* __restrict__ C1, float* __restrict__ C2,
              int M, int K, int act)
{
    const float* W    = (blockIdx.z == 0) ? W0 : (blockIdx.z == 1) ? W1 : W2;
    const float* bias = (blockIdx.z == 0) ? b0 : (blockIdx.z == 1) ? b1 : b2;
    float*       C    = (blockIdx.z == 0) ? C0 : (blockIdx.z == 1) ? C1 : C2;

    extern __shared__ __align__(16) uint32_t smu[];
    const int tid  = threadIdx.x;
    const int wid  = tid >> 5;
    const int lane = tid & 31;
    const int bn = blockIdx.x << 8;       // 256-wide N tile
    const int bm = blockIdx.y << 7;       // 128-wide M tile
    const int wm = (wid >> 2) << 5;       // warp m offset: 0,32,64,96
    const int wn = (wid & 3) << 6;        // warp n offset: 0,64,128,192
    const int r  = lane >> 2;
    const int c  = lane & 3;
    const int mtg  = (wid >> 2) << 1;     // first m16 tile index of this warp
    const int ntpg = (wid & 3) << 2;      // first n16-pair index of this warp

    float acc[2][8][4];
    #pragma unroll
    for (int i = 0; i < 2; i++)
        #pragma unroll
        for (int j = 0; j < 8; j++)
            #pragma unroll
            for (int t = 0; t < 4; t++) acc[i][j][t] = 0.f;

    const int nkb = K >> 5;
    float4 ar[2], br[4];

    // -------- global loads for one k-block --------
    auto ldg_stage = [&](int kb) {
        const int kcol = kb << 5;
        #pragma unroll
        for (int i = 0; i < 2; i++) {            // A: 1024 float4 (128 x 8)
            int f4 = tid + i * 512;
            int m  = f4 >> 3;
            int k0 = (f4 & 7) << 2;
            int gm = bm + m;
            ar[i] = (gm < M) ? *(const float4*)(A + (size_t)gm * K + kcol + k0)
                             : make_float4(0.f, 0.f, 0.f, 0.f);
        }
        #pragma unroll
        for (int i = 0; i < 4; i++) {            // B: 2048 float4 (32 x 64)
            int f4 = tid + i * 512;
            int k  = f4 >> 6;
            int n0 = (f4 & 63) << 2;
            br[i] = *(const float4*)(W + (size_t)(kcol + k) * 4096 + bn + n0);
        }
    };

    // -------- cvt + scatter into fragment layout --------
    auto sts_stage = [&](int buf) {
        uint32_t* base = smu + buf * STAGE_F;
        #pragma unroll
        for (int i = 0; i < 2; i++) {
            int f4 = tid + i * 512;
            int m  = f4 >> 3;
            int ks  = (f4 & 7) >> 1;
            int khi = f4 & 1;
            int mt  = m >> 4;
            int rr  = m & 7;
            int hi  = (m >> 3) & 1;
            int reg = hi + 2 * khi;
            uint32_t* q = base + ks * A_KS_STRIDE + mt * 132 + rr * 16 + reg;
            q[0]  = f2tf32(ar[i].x);
            q[4]  = f2tf32(ar[i].y);
            q[8]  = f2tf32(ar[i].z);
            q[12] = f2tf32(ar[i].w);
        }
        #pragma unroll
        for (int i = 0; i < 4; i++) {
            int f4 = tid + i * 512;
            int k  = f4 >> 6;
            int n0 = (f4 & 63) << 2;
            int ks   = k >> 3;
            int cc   = k & 3;
            int khi  = (k >> 2) & 1;
            int ntp  = n0 >> 4;
            int npar = (n0 >> 3) & 1;
            int r0   = n0 & 7;            // 0 or 4
            int reg  = npar * 2 + khi;
            uint32_t* q = base + B_BASE + ks * B_KS_STRIDE + ntp * 132
                        + (r0 * 4 + cc) * 4 + reg;
            q[0]  = f2tf32(br[i].x);
            q[16] = f2tf32(br[i].y);
            q[32] = f2tf32(br[i].z);
            q[48] = f2tf32(br[i].w);
        }
    };

    ldg_stage(0);

    for (int kb = 0; kb < nkb; kb++) {
        sts_stage(kb & 1);
        __syncthreads();
        if (kb + 1 < nkb) ldg_stage(kb + 1);

        const uint32_t* sm_ = smu + (kb & 1) * STAGE_F;

        #pragma unroll
        for (int ks = 0; ks < 4; ks++) {
            uint4 afv[2];
            #pragma unroll
            for (int mt = 0; mt < 2; mt++)
                afv[mt] = *(const uint4*)(sm_ + ks * A_KS_STRIDE
                                          + (mtg + mt) * 132 + lane * 4);
            uint4 bfv[4];
            #pragma unroll
            for (int p = 0; p < 4; p++)
                bfv[p] = *(const uint4*)(sm_ + B_BASE + ks * B_KS_STRIDE
                                         + (ntpg + p) * 132 + lane * 4);
            #pragma unroll
            for (int mt = 0; mt < 2; mt++)
                #pragma unroll
                for (int nt = 0; nt < 8; nt++) {
                    uint32_t bf0 = (nt & 1) ? ((const uint32_t*)&bfv[nt >> 1])[2]
                                            : ((const uint32_t*)&bfv[nt >> 1])[0];
                    uint32_t bf1 = (nt & 1) ? ((const uint32_t*)&bfv[nt >> 1])[3]
                                            : ((const uint32_t*)&bfv[nt >> 1])[1];
                    asm volatile(
                        "mma.sync.aligned.m16n8k8.row.col.f32.tf32.tf32.f32 "
                        "{%0,%1,%2,%3}, {%4,%5,%6,%7}, {%8,%9}, {%0,%1,%2,%3};"
                        : "+f"(acc[mt][nt][0]), "+f"(acc[mt][nt][1]),
                          "+f"(acc[mt][nt][2]), "+f"(acc[mt][nt][3])
                        : "r"(afv[mt].x), "r"(afv[mt].y),
                          "r"(afv[mt].z), "r"(afv[mt].w),
                          "r"(bf0), "r"(bf1));
                }
        }
        __syncthreads();
    }

    // -------- epilogue --------
    #pragma unroll
    for (int mt = 0; mt < 2; mt++) {
        int row0 = bm + wm + mt * 16 + r;
        int row1 = row0 + 8;
        #pragma unroll
        for (int nt = 0; nt < 8; nt++) {
            int col = bn + wn + nt * 8 + c * 2;
            float bb0 = bias[col], bb1 = bias[col + 1];
            if (row0 < M) {
                float v0 = acc[mt][nt][0] + bb0;
                float v1 = acc[mt][nt][1] + bb1;
                if (act) { v0 = v0 >= 0.f ? v0 : SLOPE * v0; v1 = v1 >= 0.f ? v1 : SLOPE * v1; }
                *(float2*)(C + (size_t)row0 * 4096 + col) = make_float2(v0, v1);
            }
            if (row1 < M) {
                float v2 = acc[mt][nt][2] + bb0;
                float v3 = acc[mt][nt][3] + bb1;
                if (act) { v2 = v2 >= 0.f ? v2 : SLOPE * v2; v3 = v3 >= 0.f ? v3 : SLOPE * v3; }
                *(float2*)(C + (size_t)row1 * 4096 + col) = make_float2(v2, v3);
            }
        }
    }
}

// ================= attention =================

__global__ void zero_sc_kernel(float* sc)
{
    int idx = blockIdx.x * blockDim.x + threadIdx.x;
    if (idx < Bz * 65 * 65) sc[idx] = 0.f;
}

#define SCW 81
#define SC_SMEM (2 * 128 * SCW * 4)

__global__ __launch_bounds__(256)
void attn_scores_part(const float* __restrict__ Q, const float* __restrict__ Km,
                      float* __restrict__ SC, int Sq, int Sk, int qbs, int kbs)
{
    extern __shared__ __align__(16) float sq[];
    float* sk = sq + 128 * SCW;
    __shared__ float kn[80];

    const int b  = blockIdx.y;
    const int ch = blockIdx.x;
    const int tid = threadIdx.x;
    const int ty = tid >> 4, tx = tid & 15;

    for (int e = tid; e < Sq * 128; e += 256) {
        int i  = e >> 7;
        int kk = e & 127;
        sq[kk * SCW + i] = Q[((size_t)b * qbs + i) * Dd + ch * 128 + kk];
    }
    for (int e = tid; e < Sk * 128; e += 256) {
        int j  = e >> 7;
        int kk = e & 127;
        sk[kk * SCW + j] = Km[((size_t)b * kbs + j) * Dd + ch * 128 + kk];
    }
    __syncthreads();

    if (tid < Sk) {
        float s = 0.f;
        #pragma unroll 8
        for (int kk = 0; kk < 128; kk++) {
            float v = sk[kk * SCW + tid];
            s += v * v;
        }
        kn[tid] = s;
    }
    __syncthreads();

    float acc[5][5];
    #pragma unroll
    for (int u = 0; u < 5; u++)
        #pragma unroll
        for (int v = 0; v < 5; v++) acc[u][v] = 0.f;

    #pragma unroll 4
    for (int kk = 0; kk < 128; kk++) {
        float a[5], bb[5];
        #pragma unroll
        for (int u = 0; u < 5; u++) a[u]  = sq[kk * SCW + ty * 5 + u];
        #pragma unroll
        for (int v = 0; v < 5; v++) bb[v] = sk[kk * SCW + tx * 5 + v];
        #pragma unroll
        for (int u = 0; u < 5; u++)
            #pragma unroll
            for (int v = 0; v < 5; v++) acc[u][v] += a[u] * bb[v];
    }

    #pragma unroll
    for (int u = 0; u < 5; u++) {
        int i = ty * 5 + u;
        if (i >= Sq) continue;
        #pragma unroll
        for (int v = 0; v < 5; v++) {
            int j = tx * 5 + v;
            if (j >= Sk) continue;
            atomicAdd(&SC[((size_t)b * 65 + i) * 65 + j], 2.f * acc[u][v] - kn[j]);
        }
    }
}

__global__ __launch_bounds__(32)
void softmax_kernel(float* __restrict__ SC, int Sk)
{
    int b = blockIdx.y, i = blockIdx.x;
    float* row = SC + ((size_t)b * 65 + i) * 65;
    int lane = threadIdx.x;

    float v0 = (lane      < Sk) ? row[lane]      : -1e30f;
    float v1 = (lane + 32 < Sk) ? row[lane + 32] : -1e30f;
    float v2 = (lane + 64 < Sk) ? row[lane + 64] : -1e30f;
    float mx = fmaxf(v0, fmaxf(v1, v2));
    #pragma unroll
    for (int o = 16; o; o >>= 1) mx = fmaxf(mx, __shfl_xor_sync(0xffffffff, mx, o));
    float e0 = (lane      < Sk) ? __expf(v0 - mx) : 0.f;
    float e1 = (lane + 32 < Sk) ? __expf(v1 - mx) : 0.f;
    float e2 = (lane + 64 < Sk) ? __expf(v2 - mx) : 0.f;
    float s = e0 + e1 + e2;
    #pragma unroll
    for (int o = 16; o; o >>= 1) s += __shfl_xor_sync(0xffffffff, s, o);
    float inv = 1.f / s;
    if (lane      < Sk) row[lane]      = e0 * inv;
    if (lane + 32 < Sk) row[lane + 32] = e1 * inv;
    if (lane + 64 < Sk) row[lane + 64] = e2 * inv;
}

#define AO_SMEM ((65 * 128 + 65 * 64) * 4)

__global__ __launch_bounds__(256)
void attn_out_chunk(const float* __restrict__ SC, const float* __restrict__ V,
                    float* __restrict__ Out, int Sq, int vbs)
{
    extern __shared__ __align__(16) float svs[];
    float* sw = svs + 65 * 128;

    const int b  = blockIdx.y;
    const int ch = blockIdx.x;
    const int tid = threadIdx.x;
    const int tx = tid & 31, ty = tid >> 5;

    for (int e = tid; e < Sq * 128; e += 256) {
        int i  = e >> 7;
        int kk = e & 127;
        svs[e] = V[((size_t)b * vbs + i) * Dd + ch * 128 + kk];
    }
    for (int e = tid; e < Sq * 64; e += 256) {
        int i = e >> 6;
        int j = e & 63;
        sw[e] = SC[((size_t)b * 65 + i) * 65 + j];
    }
    __syncthreads();

    float acc[8][4];
    #pragma unroll
    for (int u = 0; u < 8; u++)
        #pragma unroll
        for (int t = 0; t < 4; t++) acc[u][t] = 0.f;

    for (int i = 0; i < Sq; i++) {
        float4 v4 = *(const float4*)(svs + i * 128 + tx * 4);
        #pragma unroll
        for (int u = 0; u < 8; u++) {
            float w = sw[i * 64 + ty * 8 + u];
            acc[u][0] += w * v4.x;
            acc[u][1] += w * v4.y;
            acc[u][2] += w * v4.z;
            acc[u][3] += w * v4.w;
        }
    }

    #pragma unroll
    for (int u = 0; u < 8; u++) {
        int j = ty * 8 + u;
        *(float4*)(Out + ((size_t)b * 64 + j) * Dd + ch * 128 + tx * 4) =
            make_float4(acc[u][0], acc[u][1], acc[u][2], acc[u][3]);
    }
}

// ================= layout kernels =================
__global__ void patchify_kernel(const float* __restrict__ x, float* __restrict__ hs)
{
    int idx = blockIdx.x * blockDim.x + threadIdx.x;
    if (idx >= Bz * 64 * Dd) return;
    int d  = idx & 4095;
    int n  = (idx >> 12) & 63;
    int b  = idx >> 18;
    int cc = d & 63;
    int pp = d >> 6;
    int pr = pp >> 3, pc = pp & 7;
    int ib = n >> 3, jb = n & 7;
    int y  = jb * 8 + pr;
    int xw = ib * 8 + pc;
    hs[((size_t)b * 65 + n) * Dd + d] =
        x[(((size_t)b * 64 + cc) * 64 + y) * 64 + xw];
}

__global__ void style_kernel(const float* __restrict__ w, const float* __restrict__ sw,
                             const float* __restrict__ sb, float* __restrict__ hs)
{
    int o = blockIdx.x * blockDim.x + threadIdx.x;
    int b = blockIdx.y;
    const float* wb = w + (size_t)b * WD;
    float acc = sb[o];
    #pragma unroll 4
    for (int k = 0; k < WD; k++)
        acc += wb[k] * sw[(size_t)k * Dd + o];
    hs[((size_t)b * 65 + 64) * Dd + o] = acc;
}

__global__ void depatchify_kernel(const float* __restrict__ h, float* __restrict__ out)
{
    int idx = blockIdx.x * blockDim.x + threadIdx.x;
    if (idx >= Bz * 64 * 64 * 64) return;
    int xw = idx & 63;
    int y  = (idx >> 6) & 63;
    int cc = (idx >> 12) & 63;
    int b  = idx >> 18;
    int jb = y >> 3, pr = y & 7;
    int ib = xw >> 3, pc = xw & 7;
    int n = ib * 8 + jb;
    int d = (pr * 8 + pc) * 64 + cc;
    out[idx] = h[((size_t)b * 64 + n) * Dd + d];
}

// ================= host sequence =================
static void run_gemm3(const float* A,
                      const float* W0, const float* W1, const float* W2,
                      const float* b0, const float* b1, const float* b2,
                      float* C0, float* C1, float* C2,
                      int M, int K, int nz, int act)
{
    dim3 grid(16, (M + 127) / 128, nz);
    mma_gemm<<<grid, 512, GEMM_SMEM>>>(A, W0, W1, W2, b0, b1, b2,
                                       C0, C1, C2, M, K, act);
}

static void run_attention(const float* q, const float* k, const float* v,
                          float* sc, float* a, int Sq, int Sk,
                          int qbs, int kbs, int vbs)
{
    zero_sc_kernel<<<(Bz * 65 * 65 + 255) / 256, 256>>>(sc);
    attn_scores_part<<<dim3(32, Bz), 256, SC_SMEM>>>(q, k, sc, Sq, Sk, qbs, kbs);
    softmax_kernel<<<dim3(Sq, Bz), 32>>>(sc, Sk);
    attn_out_chunk<<<dim3(32, Bz), 256, AO_SMEM>>>(sc, v, a, Sq, vbs);
}

extern "C" void kernel_launch(void* const* d_in, const int* in_sizes, int n_in,
                              void* d_out, int out_size)
{
    const float* x          = (const float*)d_in[0];
    const float* w          = (const float*)d_in[1];
    const float* t_local    = (const float*)d_in[2];
    const float* sa_style_w = (const float*)d_in[3];
    const float* sa_style_b = (const float*)d_in[4];
    const float* sa_kk = (const float*)d_in[5];
    const float* sa_kb = (const float*)d_in[6];
    const float* sa_qk = (const float*)d_in[7];
    const float* sa_qb = (const float*)d_in[8];
    const float* sa_vk = (const float*)d_in[9];
    const float* sa_vb = (const float*)d_in[10];
    const float* sa_ok = (const float*)d_in[11];
    const float* sa_ob = (const float*)d_in[12];
    const float* ca_kk = (const float*)d_in[13];
    const float* ca_kb = (const float*)d_in[14];
    const float* ca_qk = (const float*)d_in[15];
    const float* ca_qb = (const float*)d_in[16];
    const float* ca_vk = (const float*)d_in[17];
    const float* ca_vb = (const float*)d_in[18];
    const float* ca_ok = (const float*)d_in[19];
    const float* ca_ob = (const float*)d_in[20];
    float* out = (float*)d_out;

    float *hs, *q, *k, *v, *sc, *a, *h;
    cudaGetSymbolAddress((void**)&hs, g_hs);
    cudaGetSymbolAddress((void**)&q,  g_q);
    cudaGetSymbolAddress((void**)&k,  g_k);
    cudaGetSymbolAddress((void**)&v,  g_v);
    cudaGetSymbolAddress((void**)&sc, g_sc);
    cudaGetSymbolAddress((void**)&a,  g_a);
    cudaGetSymbolAddress((void**)&h,  g_h);

    cudaFuncSetAttribute(mma_gemm, cudaFuncAttributeMaxDynamicSharedMemorySize, GEMM_SMEM);
    cudaFuncSetAttribute(attn_scores_part, cudaFuncAttributeMaxDynamicSharedMemorySize, SC_SMEM);
    cudaFuncSetAttribute(attn_out_chunk, cudaFuncAttributeMaxDynamicSharedMemorySize, AO_SMEM);

    // 1. patchify + style token -> hs (B,65,D)
    patchify_kernel<<<(Bz * 64 * Dd + 255) / 256, 256>>>(x, hs);
    style_kernel<<<dim3(Dd / 256, Bz), 256>>>(w, sa_style_w, sa_style_b, hs);

    // 2. SA q/k/v projections, fused (M=520, K=4096, z=3)
    run_gemm3(hs, sa_qk, sa_kk, sa_vk, sa_qb, sa_kb, sa_vb,
              q, k, v, Bz * 65, Dd, 3, 0);

    // 3. SA L2 attention (Sq=Sk=65, out keys 0..63)
    run_attention(q, k, v, sc, a, 65, 65, 65, 65, 65);

    // 4. SA output projection + leaky relu
    run_gemm3(a, sa_ok, sa_ok, sa_ok, sa_ob, sa_ob, sa_ob,
              h, h, h, Bz * 64, Dd, 1, 1);

    // 5. CA projections: k from h; q/v from t_local fused (z=2)
    run_gemm3(h, ca_kk, ca_kk, ca_kk, ca_kb, ca_kb, ca_kb,
              k, k, k, Bz * 64, Dd, 1, 0);
    run_gemm3(t_local, ca_qk, ca_vk, ca_vk, ca_qb, ca_vb, ca_vb,
              q, v, v, Bz * 64, TD, 2, 0);

    // 6. CA L2 attention (Sq=64, Sk=64)
    run_attention(q, k, v, sc, a, 64, 64, 64, 64, 64);

    // 7. CA output projection + leaky relu
    run_gemm3(a, ca_ok, ca_ok, ca_ok, ca_ob, ca_ob, ca_ob,
              h, h, h, Bz * 64, Dd, 1, 1);

    // 8. depatchify
    depatchify_kernel<<<(Bz * 64 * 64 * 64 + 255) / 256, 256>>>(h, out);
}